// round 15
// baseline (speedup 1.0000x reference)
#include <cuda_runtime.h>
#include <cstdint>

#define LN_EPS 1e-5f
#define D_EPS  1e-6f
#define BATCH  16
#define SEQL   2048
#define NCHUNK 32           // 32 chunks x 64 steps = 2048 (2047 real + 1 pad)

// Scratch
__device__ float g_tab[64 * 64];
__device__ float g_G[64 * 64];                     // Gram
__device__ float g_TW[64 * 64];                    // Tab @ Wr
__device__ float g_rpos[64];                       // 1/(||tab||^2 + eps)
__device__ float g_dpos[64];                       // (||tab||^2 + eps)
// per chunk: token-space C (64x64): z = C w drives both beta and w-update
__device__ float g_C[BATCH * NCHUNK * 4096];

// ---------------------------------------------------------------------------
__device__ __forceinline__ void cp_async16(uint32_t saddr, const void* gaddr) {
    asm volatile("cp.async.cg.shared.global [%0], [%1], 16;"
                 :: "r"(saddr), "l"(gaddr));
}
__device__ __forceinline__ void cp_commit() {
    asm volatile("cp.async.commit_group;");
}
__device__ __forceinline__ void cp_wait4() {
    asm volatile("cp.async.wait_group 4;");
}

// ---------------------------------------------------------------------------
// K1: per-token table (R3-proven 64-block version)
// ---------------------------------------------------------------------------
__global__ __launch_bounds__(128) void table_kernel(
    const float* __restrict__ embed, const float* __restrict__ W1,
    const float* __restrict__ b1, const float* __restrict__ W2,
    const float* __restrict__ b2, const float* __restrict__ gamma,
    const float* __restrict__ beta)
{
    __shared__ float hs[64];
    __shared__ float t1s[128];
    __shared__ float xh[2][64];
    __shared__ float red[2][2];

    const int a = blockIdx.x, tid = threadIdx.x;
    if (tid < 64) hs[tid] = embed[a * 64 + tid];
    __syncthreads();

    float acc = b1[tid];
    #pragma unroll
    for (int i = 0; i < 64; i++) acc = fmaf(hs[i], W1[i * 128 + tid], acc);
    t1s[tid] = fmaxf(acc, 0.f);
    __syncthreads();

    {
        int j = tid & 63, half = tid >> 6;
        float a2 = 0.f;
        #pragma unroll
        for (int ii = 0; ii < 64; ii++) {
            int i = half * 64 + ii;
            a2 = fmaf(t1s[i], W2[i * 64 + j], a2);
        }
        xh[half][j] = a2;
    }
    __syncthreads();

    float x = 0.f, y = 0.f;
    if (tid < 64) {
        x = hs[tid] + xh[0][tid] + xh[1][tid] + b2[tid];
        float s = x, q = x * x;
        #pragma unroll
        for (int o = 16; o > 0; o >>= 1) {
            s += __shfl_xor_sync(0xffffffffu, s, o);
            q += __shfl_xor_sync(0xffffffffu, q, o);
        }
        if ((tid & 31) == 0) { red[tid >> 5][0] = s; red[tid >> 5][1] = q; }
    }
    __syncthreads();
    if (tid < 64) {
        float S = red[0][0] + red[1][0];
        float Q = red[0][1] + red[1][1];
        float mu = S * (1.0f / 64.0f);
        float var = Q * (1.0f / 64.0f) - mu * mu;
        y = (x - mu) * rsqrtf(var + LN_EPS) * gamma[tid] + beta[tid];
        g_tab[a * 64 + tid] = y;
        float z = y * y;
        #pragma unroll
        for (int o = 16; o > 0; o >>= 1) z += __shfl_xor_sync(0xffffffffu, z, o);
        if ((tid & 31) == 0) red[tid >> 5][0] = z;
    }
    __syncthreads();
    if (tid == 0) {
        float d = red[0][0] + red[1][0] + D_EPS;
        g_dpos[a] = d;
        g_rpos[a] = 1.0f / d;
    }
}

// ---------------------------------------------------------------------------
// K2: G = Tab Tab^T and TW = Tab @ Wr.
// ---------------------------------------------------------------------------
__global__ __launch_bounds__(64) void gram_kernel(const float* __restrict__ Wr)
{
    __shared__ float T[64][65];
    const int a = blockIdx.x, t = threadIdx.x;
    for (int r = 0; r < 64; r++) T[r][t] = g_tab[r * 64 + t];
    __syncthreads();
    float g = 0.f, tw = 0.f;
    #pragma unroll
    for (int h = 0; h < 64; h++) {
        float av = T[a][h];
        g  = fmaf(av, T[t][h], g);
        tw = fmaf(av, Wr[h * 64 + t], tw);
    }
    g_G[a * 64 + t]  = g;
    g_TW[a * 64 + t] = tw;
}

// ---------------------------------------------------------------------------
// K3: per-chunk prep (R11-proven). Ainv = (I+L)^{-1}; emit token-space
//   C[a][b] = sum_{l: v_l=a} r_l * sum_{m: v_m=b} Ainv[l][m]
// ---------------------------------------------------------------------------
__global__ __launch_bounds__(64) void prep_kernel(const int* __restrict__ seq)
{
    __shared__ int   vtok[64];
    __shared__ float rr[64];
    __shared__ float Lsh[64 * 65];     // L -> Ainv -> (aliased) Csh
    __shared__ float Bsh[64 * 65];

    const int blk = blockIdx.x;
    const int b = blk >> 5, c = blk & 31;
    const int t = threadIdx.x;
    const int* sq = seq + b * SEQL;

    {
        int i = c * 64 + t;                     // reversed global step index
        int v = (i < 2047) ? sq[2046 - i] : 0;  // step 2047 is pad
        vtok[t] = v;
        rr[t]   = (i < 2047) ? g_rpos[v] : 0.f;
    }
    __syncthreads();

    // L row t (strictly lower): L[t][u] = r_u * G[v_t][v_u]
    {
        const float* gr = g_G + vtok[t] * 64;
        for (int u = 0; u < t; u++)
            Lsh[t * 65 + u] = rr[u] * gr[vtok[u]];
    }
    __syncthreads();

    // forward substitution: thread t owns column t of X = (I+L)^{-1}
    float X[64];
    #pragma unroll
    for (int i2 = 0; i2 < 64; i2++) X[i2] = (i2 == t) ? 1.f : 0.f;
    #pragma unroll
    for (int u = 0; u < 63; u++) {
        float xu = X[u];
        #pragma unroll
        for (int tt = u + 1; tt < 64; tt++)
            X[tt] = fmaf(-Lsh[tt * 65 + u], xu, X[tt]);
    }
    __syncthreads();

    // Lsh <- Ainv (row r, col t)
    #pragma unroll
    for (int i2 = 0; i2 < 64; i2++) Lsh[i2 * 65 + t] = X[i2];
    __syncthreads();

    // Bsh row t: Bsh[t][b2] = sum_{m: v_m=b2} Ainv[t][m]
    for (int b2 = 0; b2 < 64; b2++) Bsh[t * 65 + b2] = 0.f;
    for (int m = 0; m < 64; m++) Bsh[t * 65 + vtok[m]] += Lsh[t * 65 + m];
    __syncthreads();       // Lsh (Ainv) dead -> reuse as Csh

    float* Csh = Lsh;
    for (int a = 0; a < 64; a++) Csh[a * 65 + t] = 0.f;
    __syncthreads();
    // column t owned exclusively
    for (int l = 0; l < 64; l++)
        Csh[vtok[l] * 65 + t] += rr[l] * Bsh[l * 65 + t];
    __syncthreads();

    {
        float4* dst = (float4*)(g_C + (size_t)blk * 4096 + t * 64);
        const float* src = Csh + t * 65;
        #pragma unroll
        for (int j4 = 0; j4 < 16; j4++)
            dst[j4] = make_float4(src[4*j4], src[4*j4+1],
                                  src[4*j4+2], src[4*j4+3]);
    }
}

// ---------------------------------------------------------------------------
// K4: chain. 1 block/batch, 64 THREADS = 1 thread per row. No shfls.
// C streamed by cp.async (distance 5, 6 buffers, stride-68 rows); G resident.
// Per chunk (2 cheap 2-warp barriers):
//   phase1: z_j = dot(C_row_j, w)   (w broadcast reads)  -> zsh, zacc
//   phase2: w_j -= dot(G_row_j, z)  (z broadcast reads)  -> wsh
// Post: beta = d .* zacc; head -> out.
// ---------------------------------------------------------------------------
#define ASTRIDE  68
#define NBUF     6
#define OFF_CB   0                  // 6*64*68 = 26112
#define OFF_GS   26112              // 4352
#define OFF_W    30464              // 64
#define OFF_Z    30528              // 64
#define OFF_BET  30592              // 64
#define OFF_HED  30656              // 64
#define SMEM_FLOATS 30720
#define SMEM_BYTES  (SMEM_FLOATS * 4)

__global__ __launch_bounds__(64) void chain_kernel(
    const int* __restrict__ seq,
    const float* __restrict__ br, const float* __restrict__ Wo,
    const float* __restrict__ bo, float* __restrict__ out)
{
    extern __shared__ float sm[];
    float* Gs   = sm + OFF_GS;
    float* wsh  = sm + OFF_W;
    float* zsh  = sm + OFF_Z;
    float* betash = sm + OFF_BET;
    float* hed  = sm + OFF_HED;

    const int b = blockIdx.x, tid = threadIdx.x;   // tid = row j
    const int* sq = seq + b * SEQL;
    const float* Cgl = g_C + (size_t)b * NCHUNK * 4096;

    auto issue_chunk = [&](int c) {
        float* buf = sm + OFF_CB + (c % NBUF) * (64 * ASTRIDE);
        const float* src = Cgl + (size_t)c * 4096;
        #pragma unroll
        for (int k = 0; k < 16; k++) {
            int s = tid + k * 64;
            int row = s >> 4, c16 = s & 15;
            uint32_t sa = (uint32_t)__cvta_generic_to_shared(
                              buf + row * ASTRIDE + c16 * 4);
            cp_async16(sa, src + row * 64 + c16 * 4);
        }
    };

    // prologue: fill pipeline to depth 5
    #pragma unroll
    for (int c0 = 0; c0 < 5; c0++) { issue_chunk(c0); cp_commit(); }

    // stage G (stride 68, float4 stores) + w0
    for (int idx = tid; idx < 1024; idx += 64) {
        float4 gv = ((const float4*)g_G)[idx];
        *(float4*)(Gs + (idx >> 4) * ASTRIDE + (idx & 15) * 4) = gv;
    }
    float wreg = g_G[tid * 64 + sq[SEQL - 1]];
    wsh[tid] = wreg;

    float zacc = 0.f;

    for (int c = 0; c < NCHUNK; c++) {
        cp_wait4();               // buffer for chunk c complete
        __syncthreads();          // staged + prev wsh writes visible
        if (c + 5 < NCHUNK) issue_chunk(c + 5);
        cp_commit();              // uniform group counting

        const float* buf = sm + OFF_CB + (c % NBUF) * (64 * ASTRIDE);

        // --- phase 1: z_j = dot(C_row_j, w) ---
        {
            const float4* ar = (const float4*)(buf + tid * ASTRIDE);
            const float4* wr = (const float4*)wsh;
            float ax = 0.f, ay = 0.f, az = 0.f, aw = 0.f;
            #pragma unroll
            for (int k = 0; k < 16; k++) {
                float4 a = ar[k];
                float4 w = wr[k];
                ax = fmaf(a.x, w.x, ax);
                ay = fmaf(a.y, w.y, ay);
                az = fmaf(a.z, w.z, az);
                aw = fmaf(a.w, w.w, aw);
            }
            float sv = (ax + ay) + (az + aw);
            zsh[tid] = sv;
            zacc += sv;
        }
        __syncthreads();

        // --- phase 2: w_j -= dot(G_row_j, z) ---
        {
            const float4* gr = (const float4*)(Gs + tid * ASTRIDE);
            const float4* zr = (const float4*)zsh;
            float ax = 0.f, ay = 0.f, az = 0.f, aw = 0.f;
            #pragma unroll
            for (int k = 0; k < 16; k++) {
                float4 g = gr[k];
                float4 z = zr[k];
                ax = fmaf(g.x, z.x, ax);
                ay = fmaf(g.y, z.y, ay);
                az = fmaf(g.z, z.z, az);
                aw = fmaf(g.w, z.w, aw);
            }
            wreg -= (ax + ay) + (az + aw);
            wsh[tid] = wreg;
        }
    }

    // beta[j] = zacc * d_j
    betash[tid] = zacc * g_dpos[tid];
    __syncthreads();

    // head: out = (beta @ TW + br) @ Wo + bo
    {
        float acc = br[tid];
        #pragma unroll
        for (int a = 0; a < 64; a++)
            acc = fmaf(betash[a], g_TW[a * 64 + tid], acc);
        hed[tid] = acc;
    }
    __syncthreads();
    {
        float o = bo[tid];
        #pragma unroll
        for (int k = 0; k < 64; k++)
            o = fmaf(hed[k], Wo[k * 64 + tid], o);
        out[b * 64 + tid] = o;
    }
}

// ---------------------------------------------------------------------------
extern "C" void kernel_launch(void* const* d_in, const int* in_sizes, int n_in,
                              void* d_out, int out_size)
{
    const int*   seq   = (const int*)d_in[0];
    const float* embed = (const float*)d_in[1];
    const float* W1    = (const float*)d_in[2];
    const float* b1    = (const float*)d_in[3];
    const float* W2    = (const float*)d_in[4];
    const float* b2    = (const float*)d_in[5];
    const float* gamma = (const float*)d_in[6];
    const float* beta  = (const float*)d_in[7];
    const float* Wr    = (const float*)d_in[8];
    const float* br    = (const float*)d_in[9];
    const float* Wo    = (const float*)d_in[10];
    const float* bo    = (const float*)d_in[11];
    float* out = (float*)d_out;

    cudaFuncSetAttribute(chain_kernel,
                         cudaFuncAttributeMaxDynamicSharedMemorySize,
                         SMEM_BYTES);

    table_kernel<<<64, 128>>>(embed, W1, b1, W2, b2, gamma, beta);
    gram_kernel<<<64, 64>>>(Wr);
    prep_kernel<<<BATCH * NCHUNK, 64>>>(seq);
    chain_kernel<<<BATCH, 64, SMEM_BYTES>>>(seq, br, Wo, bo, out);
}

// round 16
// speedup vs baseline: 1.4285x; 1.4285x over previous
#include <cuda_runtime.h>
#include <cstdint>

#define LN_EPS 1e-5f
#define D_EPS  1e-6f
#define BATCH  16
#define SEQL   2048
#define NCHUNK 32           // 32 chunks x 64 steps = 2048 (2047 real + 1 pad)

// Scratch
__device__ float g_tab[64 * 64];
__device__ float g_G[64 * 64];                     // Gram
__device__ float g_TW[64 * 64];                    // Tab @ Wr
__device__ float g_rpos[64];                       // 1/(||tab||^2 + eps)
__device__ float g_dpos[64];                       // (||tab||^2 + eps)
// per chunk: token-space C (64x64): z = C w drives both beta and w-update
__device__ float g_C[BATCH * NCHUNK * 4096];

// ---------------------------------------------------------------------------
__device__ __forceinline__ void cp_async16(uint32_t saddr, const void* gaddr) {
    asm volatile("cp.async.cg.shared.global [%0], [%1], 16;"
                 :: "r"(saddr), "l"(gaddr));
}
__device__ __forceinline__ void cp_commit() {
    asm volatile("cp.async.commit_group;");
}
__device__ __forceinline__ void cp_wait4() {
    asm volatile("cp.async.wait_group 4;");
}

// ---------------------------------------------------------------------------
// K1: per-token table (R3-proven 64-block version)
// ---------------------------------------------------------------------------
__global__ __launch_bounds__(128) void table_kernel(
    const float* __restrict__ embed, const float* __restrict__ W1,
    const float* __restrict__ b1, const float* __restrict__ W2,
    const float* __restrict__ b2, const float* __restrict__ gamma,
    const float* __restrict__ beta)
{
    __shared__ float hs[64];
    __shared__ float t1s[128];
    __shared__ float xh[2][64];
    __shared__ float red[2][2];

    const int a = blockIdx.x, tid = threadIdx.x;
    if (tid < 64) hs[tid] = embed[a * 64 + tid];
    __syncthreads();

    float acc = b1[tid];
    #pragma unroll
    for (int i = 0; i < 64; i++) acc = fmaf(hs[i], W1[i * 128 + tid], acc);
    t1s[tid] = fmaxf(acc, 0.f);
    __syncthreads();

    {
        int j = tid & 63, half = tid >> 6;
        float a2 = 0.f;
        #pragma unroll
        for (int ii = 0; ii < 64; ii++) {
            int i = half * 64 + ii;
            a2 = fmaf(t1s[i], W2[i * 64 + j], a2);
        }
        xh[half][j] = a2;
    }
    __syncthreads();

    float x = 0.f, y = 0.f;
    if (tid < 64) {
        x = hs[tid] + xh[0][tid] + xh[1][tid] + b2[tid];
        float s = x, q = x * x;
        #pragma unroll
        for (int o = 16; o > 0; o >>= 1) {
            s += __shfl_xor_sync(0xffffffffu, s, o);
            q += __shfl_xor_sync(0xffffffffu, q, o);
        }
        if ((tid & 31) == 0) { red[tid >> 5][0] = s; red[tid >> 5][1] = q; }
    }
    __syncthreads();
    if (tid < 64) {
        float S = red[0][0] + red[1][0];
        float Q = red[0][1] + red[1][1];
        float mu = S * (1.0f / 64.0f);
        float var = Q * (1.0f / 64.0f) - mu * mu;
        y = (x - mu) * rsqrtf(var + LN_EPS) * gamma[tid] + beta[tid];
        g_tab[a * 64 + tid] = y;
        float z = y * y;
        #pragma unroll
        for (int o = 16; o > 0; o >>= 1) z += __shfl_xor_sync(0xffffffffu, z, o);
        if ((tid & 31) == 0) red[tid >> 5][0] = z;
    }
    __syncthreads();
    if (tid == 0) {
        float d = red[0][0] + red[1][0] + D_EPS;
        g_dpos[a] = d;
        g_rpos[a] = 1.0f / d;
    }
}

// ---------------------------------------------------------------------------
// K2: G = Tab Tab^T and TW = Tab @ Wr.
// ---------------------------------------------------------------------------
__global__ __launch_bounds__(64) void gram_kernel(const float* __restrict__ Wr)
{
    __shared__ float T[64][65];
    const int a = blockIdx.x, t = threadIdx.x;
    for (int r = 0; r < 64; r++) T[r][t] = g_tab[r * 64 + t];
    __syncthreads();
    float g = 0.f, tw = 0.f;
    #pragma unroll
    for (int h = 0; h < 64; h++) {
        float av = T[a][h];
        g  = fmaf(av, T[t][h], g);
        tw = fmaf(av, Wr[h * 64 + t], tw);
    }
    g_G[a * 64 + t]  = g;
    g_TW[a * 64 + t] = tw;
}

// ---------------------------------------------------------------------------
// K3: per-chunk prep (R11-proven). Ainv = (I+L)^{-1}; emit token-space
//   C[a][b] = sum_{l: v_l=a} r_l * sum_{m: v_m=b} Ainv[l][m]
// ---------------------------------------------------------------------------
__global__ __launch_bounds__(64) void prep_kernel(const int* __restrict__ seq)
{
    __shared__ int   vtok[64];
    __shared__ float rr[64];
    __shared__ float Lsh[64 * 65];     // L -> Ainv -> (aliased) Csh
    __shared__ float Bsh[64 * 65];

    const int blk = blockIdx.x;
    const int b = blk >> 5, c = blk & 31;
    const int t = threadIdx.x;
    const int* sq = seq + b * SEQL;

    {
        int i = c * 64 + t;                     // reversed global step index
        int v = (i < 2047) ? sq[2046 - i] : 0;  // step 2047 is pad
        vtok[t] = v;
        rr[t]   = (i < 2047) ? g_rpos[v] : 0.f;
    }
    __syncthreads();

    // L row t (strictly lower): L[t][u] = r_u * G[v_t][v_u]
    {
        const float* gr = g_G + vtok[t] * 64;
        for (int u = 0; u < t; u++)
            Lsh[t * 65 + u] = rr[u] * gr[vtok[u]];
    }
    __syncthreads();

    // forward substitution: thread t owns column t of X = (I+L)^{-1}
    float X[64];
    #pragma unroll
    for (int i2 = 0; i2 < 64; i2++) X[i2] = (i2 == t) ? 1.f : 0.f;
    #pragma unroll
    for (int u = 0; u < 63; u++) {
        float xu = X[u];
        #pragma unroll
        for (int tt = u + 1; tt < 64; tt++)
            X[tt] = fmaf(-Lsh[tt * 65 + u], xu, X[tt]);
    }
    __syncthreads();

    // Lsh <- Ainv (row r, col t)
    #pragma unroll
    for (int i2 = 0; i2 < 64; i2++) Lsh[i2 * 65 + t] = X[i2];
    __syncthreads();

    // Bsh row t: Bsh[t][b2] = sum_{m: v_m=b2} Ainv[t][m]
    for (int b2 = 0; b2 < 64; b2++) Bsh[t * 65 + b2] = 0.f;
    for (int m = 0; m < 64; m++) Bsh[t * 65 + vtok[m]] += Lsh[t * 65 + m];
    __syncthreads();       // Lsh (Ainv) dead -> reuse as Csh

    float* Csh = Lsh;
    for (int a = 0; a < 64; a++) Csh[a * 65 + t] = 0.f;
    __syncthreads();
    // column t owned exclusively
    for (int l = 0; l < 64; l++)
        Csh[vtok[l] * 65 + t] += rr[l] * Bsh[l * 65 + t];
    __syncthreads();

    {
        float4* dst = (float4*)(g_C + (size_t)blk * 4096 + t * 64);
        const float* src = Csh + t * 65;
        #pragma unroll
        for (int j4 = 0; j4 < 16; j4++)
            dst[j4] = make_float4(src[4*j4], src[4*j4+1],
                                  src[4*j4+2], src[4*j4+3]);
    }
}

// ---------------------------------------------------------------------------
// K4: chain. 1 block/batch, 128 threads:
//   warps 0-1 (tid<64): compute, 1 thread per row. G row pinned in registers.
//   warps 2-3 (tid>=64): cp.async staging only (LSU offload).
// Per chunk (2 barriers):
//   phase1: z_j = dot(C_row_j, w)   (C + w from smem)  -> zsh, zacc
//   phase2: w_j -= dot(Greg_j, z)   (z from smem, G in regs) -> wsh
// Post: beta = d .* zacc; head -> out.
// ---------------------------------------------------------------------------
#define ASTRIDE  68
#define NBUF     6
#define OFF_CB   0                  // 6*64*68 = 26112
#define OFF_W    26112              // 64
#define OFF_Z    26176              // 64
#define OFF_BET  26240              // 64
#define OFF_HED  26304              // 64
#define SMEM_FLOATS 26368
#define SMEM_BYTES  (SMEM_FLOATS * 4)

__global__ __launch_bounds__(128) void chain_kernel(
    const int* __restrict__ seq,
    const float* __restrict__ br, const float* __restrict__ Wo,
    const float* __restrict__ bo, float* __restrict__ out)
{
    extern __shared__ float sm[];
    float* wsh  = sm + OFF_W;
    float* zsh  = sm + OFF_Z;
    float* betash = sm + OFF_BET;
    float* hed  = sm + OFF_HED;

    const int b = blockIdx.x, tid = threadIdx.x;
    const bool is_comp = (tid < 64);
    const int j = tid & 63;                      // row for compute threads
    const int* sq = seq + b * SEQL;
    const float* Cgl = g_C + (size_t)b * NCHUNK * 4096;

    // staging threads (tid 64..127) issue 16 cp.async each per chunk
    auto issue_chunk = [&](int c) {
        float* buf = sm + OFF_CB + (c % NBUF) * (64 * ASTRIDE);
        const float* src = Cgl + (size_t)c * 4096;
        int t2 = tid - 64;
        #pragma unroll
        for (int k = 0; k < 16; k++) {
            int s = t2 + k * 64;
            int row = s >> 4, c16 = s & 15;
            uint32_t sa = (uint32_t)__cvta_generic_to_shared(
                              buf + row * ASTRIDE + c16 * 4);
            cp_async16(sa, src + row * 64 + c16 * 4);
        }
    };

    // G row pinned in registers (compute threads); w0
    float4 gro[16];
    float wreg = 0.f;
    if (is_comp) {
        const float4* grow = (const float4*)(g_G + j * 64);
        #pragma unroll
        for (int k = 0; k < 16; k++) gro[k] = grow[k];
        wreg = g_G[j * 64 + sq[SEQL - 1]];
        wsh[j] = wreg;
    } else {
        // prologue: fill pipeline to depth 5
        #pragma unroll
        for (int c0 = 0; c0 < 5; c0++) { issue_chunk(c0); cp_commit(); }
    }

    float zacc = 0.f;

    for (int c = 0; c < NCHUNK; c++) {
        if (!is_comp) cp_wait4();     // buffer for chunk c complete
        __syncthreads();              // staged + prev wsh writes visible
        if (!is_comp) {
            if (c + 5 < NCHUNK) issue_chunk(c + 5);
            cp_commit();              // uniform group counting (stage warps)
        }

        if (is_comp) {
            const float* buf = sm + OFF_CB + (c % NBUF) * (64 * ASTRIDE);

            // --- phase 1: z_j = dot(C_row_j, w) ---
            const float4* ar = (const float4*)(buf + j * ASTRIDE);
            const float4* wr = (const float4*)wsh;
            float ax = 0.f, ay = 0.f, az = 0.f, aw = 0.f;
            #pragma unroll
            for (int k = 0; k < 16; k++) {
                float4 a = ar[k];
                float4 w = wr[k];
                ax = fmaf(a.x, w.x, ax);
                ay = fmaf(a.y, w.y, ay);
                az = fmaf(a.z, w.z, az);
                aw = fmaf(a.w, w.w, aw);
            }
            float sv = (ax + ay) + (az + aw);
            zsh[j] = sv;
            zacc += sv;
        }
        __syncthreads();

        if (is_comp) {
            // --- phase 2: w_j -= dot(Greg_j, z) ---
            const float4* zr = (const float4*)zsh;
            float ax = 0.f, ay = 0.f, az = 0.f, aw = 0.f;
            #pragma unroll
            for (int k = 0; k < 16; k++) {
                float4 g = gro[k];
                float4 z = zr[k];
                ax = fmaf(g.x, z.x, ax);
                ay = fmaf(g.y, z.y, ay);
                az = fmaf(g.z, z.z, az);
                aw = fmaf(g.w, z.w, aw);
            }
            wreg -= (ax + ay) + (az + aw);
            wsh[j] = wreg;
        }
    }

    // beta[j] = zacc * d_j
    if (is_comp) betash[j] = zacc * g_dpos[j];
    __syncthreads();

    // head: out = (beta @ TW + br) @ Wo + bo
    if (is_comp) {
        float acc = br[j];
        #pragma unroll
        for (int a = 0; a < 64; a++)
            acc = fmaf(betash[a], g_TW[a * 64 + j], acc);
        hed[j] = acc;
    }
    __syncthreads();
    if (is_comp) {
        float o = bo[j];
        #pragma unroll
        for (int k = 0; k < 64; k++)
            o = fmaf(hed[k], Wo[k * 64 + j], o);
        out[b * 64 + j] = o;
    }
}

// ---------------------------------------------------------------------------
extern "C" void kernel_launch(void* const* d_in, const int* in_sizes, int n_in,
                              void* d_out, int out_size)
{
    const int*   seq   = (const int*)d_in[0];
    const float* embed = (const float*)d_in[1];
    const float* W1    = (const float*)d_in[2];
    const float* b1    = (const float*)d_in[3];
    const float* W2    = (const float*)d_in[4];
    const float* b2    = (const float*)d_in[5];
    const float* gamma = (const float*)d_in[6];
    const float* beta  = (const float*)d_in[7];
    const float* Wr    = (const float*)d_in[8];
    const float* br    = (const float*)d_in[9];
    const float* Wo    = (const float*)d_in[10];
    const float* bo    = (const float*)d_in[11];
    float* out = (float*)d_out;

    cudaFuncSetAttribute(chain_kernel,
                         cudaFuncAttributeMaxDynamicSharedMemorySize,
                         SMEM_BYTES);

    table_kernel<<<64, 128>>>(embed, W1, b1, W2, b2, gamma, beta);
    gram_kernel<<<64, 64>>>(Wr);
    prep_kernel<<<BATCH * NCHUNK, 64>>>(seq);
    chain_kernel<<<BATCH, 128, SMEM_BYTES>>>(seq, br, Wo, bo, out);
}